// round 10
// baseline (speedup 1.0000x reference)
#include <cuda_runtime.h>
#include <cuda_fp16.h>
#include <cstdint>

// Shapes (fixed): x (2048,4096) fp32, values (1024,64,64) fp32, bias (4096,),
// block_rows/cols (1024,) int32 in [0,64), out (2048,4096) fp32.
#define KDIM  4096
#define MDIM  4096
#define TTOK  2048
#define NBMAX 1024
#define MT    256            // tokens per CTA (8 slabs)
#define NT    64             // out features per CTA (one row block)

// Half-block staging: K=32 per stage, row pitch 40 fp16 = 80 B (16B multiple,
// 80*r mod 128 distinct for r=0..7 -> ldmatrix conflict-free).
#define PITCHB  80
#define XB      (256 * PITCHB)        // 20480
#define VB      (64  * PITCHB)        // 5120
#define STAGE   (XB + VB)             // 25600
#define NSTG    4
#define SMEM_TOTAL (NSTG * STAGE)     // 102400 -> 2 CTAs/SM

// ---- device scratch (static globals; no allocations allowed) ----
__device__ __half g_xh[TTOK * KDIM];          // 16 MB
__device__ __half g_vh[NBMAX * 64 * 64];      // 8 MB
__device__ int g_row_list[64 * NBMAX];
__device__ int g_row_cnt[64];
__device__ int g_row_order[64];

// ---- PTX helpers (baseline sm_80+ features only) ----
__device__ __forceinline__ uint32_t smem_u32(const void* p) {
    uint32_t a;
    asm("{ .reg .u64 t; cvta.to.shared.u64 t, %1; cvt.u32.u64 %0, t; }" : "=r"(a) : "l"(p));
    return a;
}
__device__ __forceinline__ void cp_async16(uint32_t saddr, const void* gaddr) {
    asm volatile("cp.async.cg.shared.global [%0], [%1], 16;" :: "r"(saddr), "l"(gaddr));
}
#define CP_COMMIT() asm volatile("cp.async.commit_group;" ::: "memory")
#define CP_WAIT(n)  asm volatile("cp.async.wait_group %0;" :: "n"(n) : "memory")

__device__ __forceinline__ void ldsm_x4(uint32_t* r, uint32_t addr) {
    asm volatile("ldmatrix.sync.aligned.m8n8.x4.shared.b16 {%0,%1,%2,%3}, [%4];"
                 : "=r"(r[0]), "=r"(r[1]), "=r"(r[2]), "=r"(r[3]) : "r"(addr));
}
__device__ __forceinline__ void mma_f16(float* d, const uint32_t* a, uint32_t b0, uint32_t b1) {
    asm volatile(
        "mma.sync.aligned.m16n8k16.row.col.f32.f16.f16.f32 "
        "{%0,%1,%2,%3}, {%4,%5,%6,%7}, {%8,%9}, {%0,%1,%2,%3};"
        : "+f"(d[0]), "+f"(d[1]), "+f"(d[2]), "+f"(d[3])
        : "r"(a[0]), "r"(a[1]), "r"(a[2]), "r"(a[3]), "r"(b0), "r"(b1));
}

__device__ __forceinline__ float gelu_tanh(float v) {
    float inner = 0.7978845608f * (v + 0.044715f * v * v * v);
    return 0.5f * v * (1.0f + tanhf(inner));
}

// ---------------------------------------------------------------------------
// Pre-pass 1 (fused): fp32 -> fp16 for both x and values in one launch.
// Blocks [0, XBLK) handle x; blocks [XBLK, XBLK+VBLK) handle values.
// ---------------------------------------------------------------------------
#define XBLK 2048
#define VBLK 1024
__global__ void __launch_bounds__(256) convert_all_kernel(
    const float* __restrict__ x, const float* __restrict__ values,
    int nx4, int nv4)
{
    const int b = blockIdx.x;
    const float4* s4;
    uint2* dst;
    int n4, start, stride;
    if (b < XBLK) {
        s4 = (const float4*)x; dst = (uint2*)g_xh; n4 = nx4;
        start = b * 256 + threadIdx.x; stride = XBLK * 256;
    } else {
        s4 = (const float4*)values; dst = (uint2*)g_vh; n4 = nv4;
        start = (b - XBLK) * 256 + threadIdx.x; stride = VBLK * 256;
    }
    for (int i = start; i < n4; i += stride) {
        float4 v = s4[i];
        __half2 a = __floats2half2_rn(v.x, v.y);
        __half2 c = __floats2half2_rn(v.z, v.w);
        uint2 o{*(uint32_t*)&a, *(uint32_t*)&c};
        dst[i] = o;
    }
}

// ---------------------------------------------------------------------------
// Pre-pass 2 (fused): lists + LPT order in ONE single-CTA kernel.
// 32 warps; warp w builds rows w and w+32. Then 64 threads compute ranks.
// ---------------------------------------------------------------------------
__global__ void __launch_bounds__(1024) lists_order_kernel(
    const int* __restrict__ brows, int nb)
{
    __shared__ int cnts[64];
    const int warp = threadIdx.x >> 5, lane = threadIdx.x & 31;
    for (int r = warp; r < 64; r += 32) {
        int cnt = 0;
        for (int base = 0; base < nb; base += 32) {
            int n = base + lane;
            int row = (n < nb) ? brows[n] : -1;
            unsigned m = __ballot_sync(0xFFFFFFFFu, row == r);
            if (row == r)
                g_row_list[r * NBMAX + cnt + __popc(m & ((1u << lane) - 1u))] = n;
            cnt += __popc(m);
        }
        if (lane == 0) { g_row_cnt[r] = cnt; cnts[r] = cnt; }
    }
    __syncthreads();
    const int i = threadIdx.x;
    if (i < 64) {
        const int c = cnts[i];
        int rank = 0;
        #pragma unroll
        for (int j = 0; j < 64; j++) {
            const int cj = cnts[j];
            rank += (cj > c) || (cj == c && j < i);
        }
        g_row_order[rank] = i;
    }
}

// ---------------------------------------------------------------------------
// Half-stage loader: K=32 slice of X (256 rows) and V into stage s.
// 256 threads: X 1024 chunks (4/thread) + V 256 chunks (1/thread).
// ---------------------------------------------------------------------------
__device__ __forceinline__ void load_half(uint32_t sb, int s, int n, int c, int kh,
                                          int t0, int tid)
{
    const uint32_t xs = sb + s * STAGE;
    const uint32_t vs = xs + XB;
    const int k0 = c * 64 + kh * 32;
    #pragma unroll
    for (int i = 0; i < 4; i++) {
        const int id = tid + i * 256;
        const int row = id >> 2, cb = id & 3;
        const size_t g = (size_t)(t0 + row) * KDIM + k0 + cb * 8;
        cp_async16(xs + row * PITCHB + cb * 16, g_xh + g);
    }
    {
        const int row = tid >> 2, cb = tid & 3;
        const size_t g = (size_t)n * 4096 + row * 64 + kh * 32 + cb * 8;
        cp_async16(vs + row * PITCHB + cb * 16, g_vh + g);
    }
}

// ---------------------------------------------------------------------------
// Main kernel: 256 threads = 8 warps in 4(m) x 2(n), warp tile 64x32 over a
// 256x64 CTA tile. fp16 HMMA, fp32 accum, 4-stage K32 cp.async pipeline.
// ---------------------------------------------------------------------------
__global__ void __launch_bounds__(256, 2) fsl_hmma_kernel(
    const float* __restrict__ bias,
    const int*   __restrict__ bcols,
    float*       __restrict__ out)
{
    extern __shared__ char smem[];
    const uint32_t sb = smem_u32(smem);
    const int tid  = threadIdx.x;
    const int warp = tid >> 5;
    const int lane = tid & 31;
    const int slab = blockIdx.x & 7;           // 8 slabs of 256 tokens
    const int r    = g_row_order[blockIdx.x >> 3];
    const int t0   = slab * MT;

    const int wt = (warp >> 1) * 64;           // warp m-offset (0,64,128,192)
    const int wn = (warp & 1) * 32;            // warp n-offset (0,32)

    const int cnt   = g_row_cnt[r];
    const int total = 2 * cnt;                 // half-block stages
    const int* list = &g_row_list[r * NBMAX];

    float acc[4][4][4];                        // [mi][nj][q] : 64 regs
    #pragma unroll
    for (int mi = 0; mi < 4; mi++)
        #pragma unroll
        for (int nj = 0; nj < 4; nj++)
            #pragma unroll
            for (int q = 0; q < 4; q++) acc[mi][nj][q] = 0.0f;

    // ldmatrix lane-address components (mapping validated R4-R9)
    const int a_m = (lane & 7) + ((lane >> 3) & 1) * 8;
    const int a_k = (lane >> 4) * 8;
    const int b_n = (lane & 7) + ((lane >> 4) & 1) * 8;
    const int b_k = ((lane >> 3) & 1) * 8;

    // Prologue: prime 3 of 4 stages. Stage j = block list[j>>1], half j&1.
    #pragma unroll
    for (int j = 0; j < 3; j++) {
        if (j < total) {
            const int n = list[j >> 1];
            load_half(sb, j, n, __ldg(&bcols[n]), j & 1, t0, tid);
        }
        CP_COMMIT();
    }

    for (int i = 0; i < total; i++) {
        CP_WAIT(2);
        __syncthreads();

        if (i + 3 < total) {
            const int j = i + 3;
            const int n = list[j >> 1];
            load_half(sb, (i + 3) & 3, n, __ldg(&bcols[n]), j & 1, t0, tid);
        }
        CP_COMMIT();

        const uint32_t xs = sb + (i & 3) * STAGE;
        const uint32_t vs = xs + XB;

        #pragma unroll
        for (int kc = 0; kc < 2; kc++) {
            uint32_t ah[4][4], bh[2][4];
            const uint32_t ao = (wt + a_m) * PITCHB + (kc * 16 + a_k) * 2;
            const uint32_t bo = (wn + b_n) * PITCHB + (kc * 16 + b_k) * 2;
            #pragma unroll
            for (int mi = 0; mi < 4; mi++)
                ldsm_x4(ah[mi], xs + ao + mi * 16 * PITCHB);
            #pragma unroll
            for (int j = 0; j < 2; j++)
                ldsm_x4(bh[j], vs + bo + j * 16 * PITCHB);
            #pragma unroll
            for (int mi = 0; mi < 4; mi++)
                #pragma unroll
                for (int j = 0; j < 2; j++) {
                    mma_f16(acc[mi][2 * j + 0], ah[mi], bh[j][0], bh[j][1]);
                    mma_f16(acc[mi][2 * j + 1], ah[mi], bh[j][2], bh[j][3]);
                }
        }
    }

    // Epilogue: bias + tanh-GELU, float2 stores.
    const int row0 = lane >> 2;
    const int cp2  = (lane & 3) * 2;
    #pragma unroll
    for (int mi = 0; mi < 4; mi++) {
        #pragma unroll
        for (int nj = 0; nj < 4; nj++) {
            const int nb = wn + nj * 8 + cp2;
            const float b0 = __ldg(&bias[r * 64 + nb]);
            const float b1 = __ldg(&bias[r * 64 + nb + 1]);
            #pragma unroll
            for (int h = 0; h < 2; h++) {
                const int m = wt + mi * 16 + row0 + h * 8;
                float2 o;
                o.x = gelu_tanh(acc[mi][nj][2 * h + 0] + b0);
                o.y = gelu_tanh(acc[mi][nj][2 * h + 1] + b1);
                *(float2*)&out[(size_t)(t0 + m) * MDIM + r * 64 + nb] = o;
            }
        }
    }
}

// ---------------------------------------------------------------------------
extern "C" void kernel_launch(void* const* d_in, const int* in_sizes, int n_in,
                              void* d_out, int out_size)
{
    const float* x      = (const float*)d_in[0];
    const float* values = (const float*)d_in[1];
    const float* bias   = (const float*)d_in[2];
    const int*   brows  = (const int*)d_in[3];
    const int*   bcols  = (const int*)d_in[4];
    float*       out    = (float*)d_out;

    const int n_blocks = in_sizes[3];
    const int x_elems  = in_sizes[0];
    const int v_elems  = in_sizes[1];

    cudaFuncSetAttribute(fsl_hmma_kernel,
                         cudaFuncAttributeMaxDynamicSharedMemorySize, SMEM_TOTAL);

    convert_all_kernel<<<XBLK + VBLK, 256>>>(x, values, x_elems / 4, v_elems / 4);
    lists_order_kernel<<<1, 1024>>>(brows, n_blocks);

    fsl_hmma_kernel<<<512, 256, SMEM_TOTAL>>>(bias, bcols, out);   // 8 slabs x 64 rows
}